// round 3
// baseline (speedup 1.0000x reference)
#include <cuda_runtime.h>
#include <cstdint>
#include <cstddef>

// Problem constants
#define NSAMP   4096
#define IDIM    512
#define HDIM    128
#define LSTRIDE (HDIM + HDIM*HDIM)   // 16512 rows of W per layer
#define NLAYER  3

// Tiling
#define NB      32                   // samples per CTA
#define KC      64                   // K-chunk staged in smem
#define NSTAGE  (IDIM/KC)            // 8
#define XPITCH  516                  // int_x smem pitch (floats)
#define HPITCH  132                  // h smem pitch
#define BPITCH  68                   // W-chunk smem pitch (floats)
#define THREADS 256

#define SMEM_FLOATS (NB*XPITCH + NB*HPITCH + 2*HDIM*BPITCH)
#define SMEM_BYTES  (SMEM_FLOATS*4)

// Packed dual-fp32 FMA (Blackwell): d = a*b + d componentwise on f32 pairs.
__device__ __forceinline__ void fma2(unsigned long long &c, unsigned long long a,
                                     unsigned long long b) {
    asm("fma.rn.f32x2 %0, %1, %2, %0;" : "+l"(c) : "l"(a), "l"(b));
}

__device__ __forceinline__ void cp16(float* s, const float* g) {
    unsigned sa = (unsigned)__cvta_generic_to_shared(s);
    asm volatile("cp.async.cg.shared.global [%0], [%1], 16;" :: "r"(sa), "l"(g));
}
__device__ __forceinline__ void cp_commit() { asm volatile("cp.async.commit_group;"); }
__device__ __forceinline__ void cp_wait0()  { asm volatile("cp.async.wait_group 0;"); }

// Fully fused InteractionNet, 256 threads (2 warps/SMSP for latency hiding).
// Per CTA: NB=32 samples end-to-end across 3 layers. Per layer, 129 chunks
// (128 weight chunks + 1 bias chunk); each chunk is C[128q x 32n] =
// Wrows[128 x 512] @ int_x[32 x 512]^T via f32x2 packed FMAs, folded as
//   h_next[n,q] += (dot + b[row]) * (chunk<128 ? h[n,chunk] : 1).
// W streams through a double-buffered smem stage with cross-chunk and
// cross-layer prefetch (no pipeline bubble at chunk boundaries).
__global__ void __launch_bounds__(THREADS, 1)
inet_kernel(const float* __restrict__ gx_int, const float* __restrict__ gx,
            const float* __restrict__ gW, const float* __restrict__ gb,
            float* __restrict__ gout)
{
    extern __shared__ float smem[];
    float* xs = smem;                       // [NB][XPITCH]  int_x tile (resident)
    float* hs = xs + NB*XPITCH;             // [NB][HPITCH]  current activation
    float* Bs = hs + NB*HPITCH;             // [2][HDIM][BPITCH] W-chunk stages

    const int tid = threadIdx.x;
    const int n0  = blockIdx.x * NB;
    const int tqg = tid & 15;               // q = tqg + 16*j, j=0..7
    const int tng = tid >> 4;               // n = tng*2 + i, i=0..1  (tng 0..15)
    const int wr  = tid >> 1;               // W row (0..127) this thread stages
    const int wo  = (tid & 1) * 32;         // half-stage offset within KC floats

    // Stage the per-CTA int_x tile (NB x 512) and initial h = x (NB x 128).
    for (int i = tid; i < NB*(IDIM/4); i += THREADS) {
        int n  = i >> 7;
        int k4 = i & 127;
        cp16(&xs[n*XPITCH + k4*4], &gx_int[(size_t)(n0+n)*IDIM + (size_t)k4*4]);
    }
    for (int i = tid; i < NB*(HDIM/4); i += THREADS) {
        int n  = i >> 5;
        int q4 = i & 31;
        cp16(&hs[n*HPITCH + q4*4], &gx[(size_t)(n0+n)*HDIM + (size_t)q4*4]);
    }
    cp_commit(); cp_wait0();
    __syncthreads();

    int buf = 0;
    // Preload layer 0, chunk 0 (rows base+HDIM+0*HDIM), stage 0 into buffer 0.
    {
        const float* src = gW + (size_t)(HDIM + wr) * IDIM + wo;
        float* dst = &Bs[wr*BPITCH + wo];
        #pragma unroll
        for (int v = 0; v < 8; ++v) cp16(dst + v*4, src + v*4);
        cp_commit();
    }

    for (int layer = 0; layer < NLAYER; ++layer) {
        const int base = layer * LSTRIDE;

        float hn[2][8];
        #pragma unroll
        for (int i = 0; i < 2; ++i)
            #pragma unroll
            for (int j = 0; j < 8; ++j) hn[i][j] = 0.f;

        for (int c = 0; c <= HDIM; ++c) {
            // c < 128: weight chunk p=c -> rows base+128+c*128+q, multiplier h[n,c]
            // c == 128: bias chunk     -> rows base+q,            multiplier 1
            const int rowbase = base + (c < HDIM ? HDIM + c*HDIM : 0);

            unsigned long long acc[2][8];
            #pragma unroll
            for (int i = 0; i < 2; ++i)
                #pragma unroll
                for (int j = 0; j < 8; ++j) acc[i][j] = 0ull;

            for (int s = 0; s < NSTAGE; ++s) {
                cp_wait0();
                __syncthreads();            // stage data in `buf` visible to all

                // Prefetch into buf^1: next stage, else next chunk's stage 0,
                // else next layer's chunk 0 stage 0.
                {
                    const float* src = nullptr;
                    if (s + 1 < NSTAGE) {
                        src = gW + (size_t)(rowbase + wr)*IDIM + (s+1)*KC + wo;
                    } else if (c < HDIM) {
                        const int nrb = base + (c+1 < HDIM ? HDIM + (c+1)*HDIM : 0);
                        src = gW + (size_t)(nrb + wr)*IDIM + wo;
                    } else if (layer + 1 < NLAYER) {
                        src = gW + (size_t)(base + LSTRIDE + HDIM + wr)*IDIM + wo;
                    }
                    if (src) {
                        float* dst = &Bs[(buf^1)*HDIM*BPITCH + wr*BPITCH + wo];
                        #pragma unroll
                        for (int v = 0; v < 8; ++v) cp16(dst + v*4, src + v*4);
                        cp_commit();
                    }
                }

                // Compute stage s: two f32 lanes accumulate k-even/k-odd sums.
                const float* bb = &Bs[buf*HDIM*BPITCH];
                const int kbase = s*KC;
                #pragma unroll 4
                for (int kk = 0; kk < KC; kk += 2) {
                    unsigned long long av[2], bv[8];
                    #pragma unroll
                    for (int i = 0; i < 2; ++i)
                        av[i] = *reinterpret_cast<const unsigned long long*>(
                                    &xs[(tng*2+i)*XPITCH + kbase + kk]);
                    #pragma unroll
                    for (int j = 0; j < 8; ++j)
                        bv[j] = *reinterpret_cast<const unsigned long long*>(
                                    &bb[(tqg + 16*j)*BPITCH + kk]);
                    #pragma unroll
                    for (int i = 0; i < 2; ++i)
                        #pragma unroll
                        for (int j = 0; j < 8; ++j)
                            fma2(acc[i][j], av[i], bv[j]);
                }
                buf ^= 1;
            }

            // Fold chunk into h_next.
            float m[2];
            #pragma unroll
            for (int i = 0; i < 2; ++i)
                m[i] = (c < HDIM) ? hs[(tng*2+i)*HPITCH + c] : 1.0f;
            #pragma unroll
            for (int j = 0; j < 8; ++j) {
                const float brow = __ldg(&gb[rowbase + tqg + 16*j]);
                #pragma unroll
                for (int i = 0; i < 2; ++i) {
                    union { unsigned long long u; float2 f; } cv;
                    cv.u = acc[i][j];
                    hn[i][j] += (cv.f.x + cv.f.y + brow) * m[i];
                }
            }
        }

        __syncthreads();
        if (layer < NLAYER-1) {
            #pragma unroll
            for (int i = 0; i < 2; ++i)
                #pragma unroll
                for (int j = 0; j < 8; ++j) {
                    float v = hn[i][j];
                    hs[(tng*2+i)*HPITCH + tqg + 16*j] = v > 0.f ? v : 0.f; // relu
                }
            __syncthreads();
        } else {
            #pragma unroll
            for (int i = 0; i < 2; ++i)
                #pragma unroll
                for (int j = 0; j < 8; ++j)
                    gout[(size_t)(n0 + tng*2 + i)*HDIM + tqg + 16*j] = hn[i][j];
        }
    }
}

extern "C" void kernel_launch(void* const* d_in, const int* in_sizes, int n_in,
                              void* d_out, int out_size)
{
    // Identify inputs by element count (robust to metadata order):
    // int_x: 4096*512, x: 4096*128, W: 49536*512, b: 49536
    const float *int_x = nullptr, *x = nullptr, *W = nullptr, *b = nullptr;
    for (int i = 0; i < n_in; ++i) {
        const int sz = in_sizes[i];
        if      (sz == NSAMP*IDIM)              int_x = (const float*)d_in[i];
        else if (sz == NSAMP*HDIM)              x     = (const float*)d_in[i];
        else if (sz == NLAYER*LSTRIDE*IDIM)     W     = (const float*)d_in[i];
        else if (sz == NLAYER*LSTRIDE)          b     = (const float*)d_in[i];
    }

    cudaFuncSetAttribute(inet_kernel, cudaFuncAttributeMaxDynamicSharedMemorySize,
                         SMEM_BYTES);
    inet_kernel<<<NSAMP/NB, THREADS, SMEM_BYTES>>>(int_x, x, W, b, (float*)d_out);
}

// round 5
// speedup vs baseline: 2.0465x; 2.0465x over previous
#include <cuda_runtime.h>
#include <cuda_bf16.h>
#include <cstdint>
#include <cstddef>

// ---------------- problem constants ----------------
#define NSAMP   4096
#define IDIM    512
#define HDIM    128
#define LSTRIDE (HDIM + HDIM*HDIM)       // 16512 rows of W per layer
#define NLAYER  3

// ---------------- tiling ----------------
#define NB      32                        // samples per CTA (GEMM N)
#define CHUNKS  129                       // 128 weight chunks + 1 x-chunk
#define SPC     8                         // 64-k slabs per chunk (K=512)
#define PSEUDO  3                         // bias-fold pseudo slabs (K=192, zero-padded)
#define SPL     (CHUNKS*SPC + PSEUDO)     // 1035 slabs per layer
#define NSLAB   (NLAYER*SPL)              // 3105 slabs total
static_assert(NSLAB % 3 == 0, "wrap-prefetch slot map needs NSLAB % 3 == 0");

#define WSLAB   32768                     // [128 x 64] bf16, hi(16K) + lo(16K), SW128
#define ZSLAB   8192                      // [32 x 64]  bf16, hi(4K)  + lo(4K),  SW128

#define XP      520                       // xs pitch (floats)
#define HP      132                       // hs pitch (floats)

#define OFF_W   0                         // 3 * 32768 = 98304
#define OFF_Z   (3*WSLAB)                 // 2 * 8192  = 16384
#define OFF_X   (OFF_Z + 2*ZSLAB)         // 32*520*4  = 66560
#define OFF_H   (OFF_X + NB*XP*4)         // 32*132*4  = 16896
#define SMEM_ALLOC (OFF_H + NB*HP*4 + 1024)

#define THREADS 256

#define SW128(x) ((x) ^ (((x) >> 3) & 0x70))

// ---------------- ptx helpers ----------------
__device__ __forceinline__ uint32_t smem_u32(const void* p) {
    uint32_t a;
    asm("{ .reg .u64 t; cvta.to.shared.u64 t, %1; cvt.u32.u64 %0, t; }" : "=r"(a) : "l"(p));
    return a;
}
__device__ __forceinline__ void cp16(uint32_t s, const void* g) {
    asm volatile("cp.async.cg.shared.global [%0], [%1], 16;" :: "r"(s), "l"(g));
}
#define CP_COMMIT() asm volatile("cp.async.commit_group;" ::: "memory")
#define CP_WAIT1()  asm volatile("cp.async.wait_group 1;" ::: "memory")
#define CP_WAIT0()  asm volatile("cp.async.wait_group 0;" ::: "memory")

__device__ __forceinline__ void ldsm4(uint32_t& r0, uint32_t& r1, uint32_t& r2,
                                      uint32_t& r3, uint32_t addr) {
    asm volatile("ldmatrix.sync.aligned.m8n8.x4.shared.b16 {%0,%1,%2,%3}, [%4];"
                 : "=r"(r0), "=r"(r1), "=r"(r2), "=r"(r3) : "r"(addr));
}
__device__ __forceinline__ void mma_bf16(float* d, const uint32_t* a,
                                         uint32_t b0, uint32_t b1) {
    asm volatile(
        "mma.sync.aligned.m16n8k16.row.col.f32.bf16.bf16.f32 "
        "{%0,%1,%2,%3}, {%4,%5,%6,%7}, {%8,%9}, {%0,%1,%2,%3};"
        : "+f"(d[0]), "+f"(d[1]), "+f"(d[2]), "+f"(d[3])
        : "r"(a[0]), "r"(a[1]), "r"(a[2]), "r"(a[3]), "r"(b0), "r"(b1));
}
__device__ __forceinline__ void split2(float v0, float v1, unsigned& hi, unsigned& lo) {
    __nv_bfloat16 h0 = __float2bfloat16(v0), h1 = __float2bfloat16(v1);
    float r0 = v0 - __bfloat162float(h0);
    float r1 = v1 - __bfloat162float(h1);
    __nv_bfloat16 l0 = __float2bfloat16(r0), l1 = __float2bfloat16(r1);
    hi = (unsigned)__bfloat16_as_ushort(h0) | ((unsigned)__bfloat16_as_ushort(h1) << 16);
    lo = (unsigned)__bfloat16_as_ushort(l0) | ((unsigned)__bfloat16_as_ushort(l1) << 16);
}

// W pack: per-slab 32KB images (hi 16KB + lo 16KB), pre-swizzled, in stream order.
__device__ __align__(16) unsigned char g_wpack[(size_t)NSLAB * WSLAB];

// ---------------- prep: split W/b to bf16 hi/lo slab images ----------------
__global__ void prep_kernel(const float* __restrict__ W, const float* __restrict__ b) {
    const int s    = blockIdx.x;
    const int l    = s / SPL;
    const int sl   = s - l * SPL;
    const int base = l * LSTRIDE;
    unsigned char* dst = g_wpack + (size_t)s * WSLAB;

    for (int task = threadIdx.x; task < 1024; task += blockDim.x) {
        const int r = task >> 3, kb = task & 7;         // row 0..127, 8-elem k block
        float v[8];
        if (sl < CHUNKS * SPC) {
            const int c = sl >> 3, j = sl & 7;
            const int row = base + (c < HDIM ? HDIM + c * HDIM + r : r);
            const float* src = W + (size_t)row * IDIM + j * 64 + kb * 8;
            #pragma unroll
            for (int e = 0; e < 8; ++e) v[e] = src[e];
        } else {                                        // bias-fold pseudo slab
            const int j = sl - CHUNKS * SPC;
            #pragma unroll
            for (int e = 0; e < 8; ++e) {
                const int kg = j * 64 + kb * 8 + e;
                v[e] = (kg < HDIM) ? b[base + HDIM + kg * HDIM + r]
                                   : (kg == HDIM ? b[base + r] : 0.f);
            }
        }
        unsigned hi[4], lo[4];
        #pragma unroll
        for (int e = 0; e < 4; ++e) split2(v[2*e], v[2*e+1], hi[e], lo[e]);
        const unsigned off = SW128(r * 128 + kb * 16);
        *(uint4*)(dst + off)         = make_uint4(hi[0], hi[1], hi[2], hi[3]);
        *(uint4*)(dst + 16384 + off) = make_uint4(lo[0], lo[1], lo[2], lo[3]);
    }
}

// ---------------- main fused kernel ----------------
__global__ void __launch_bounds__(THREADS, 1)
inet_mma_kernel(const float* __restrict__ gx_int, const float* __restrict__ gx,
                float* __restrict__ gout)
{
    extern __shared__ __align__(16) unsigned char smraw[];
    const uint32_t sb0 = smem_u32(smraw);
    const uint32_t sb  = (sb0 + 1023) & ~1023u;        // 1024-align for SW128
    unsigned char* sm  = smraw + (sb - sb0);
    float* xs = (float*)(sm + OFF_X);
    float* hs = (float*)(sm + OFF_H);

    const int tid = threadIdx.x;
    const int wid = tid >> 5, lid = tid & 31;
    const int n0  = blockIdx.x * NB;

    // Per-lane ldmatrix offset bases (bytes, pre-swizzle).
    const int g  = lid >> 3, lr = lid & 7;
    const int aoff = (16*wid + (g & 1)*8 + lr) * 128 + (g >> 1) * 16;  // A: W rows
    const int boff = ((g >> 1)*8 + lr) * 128 + (g & 1) * 16;           // B: Z rows

    // Stage int_x tile (fp32) and initial h = x.
    for (int i = tid; i < NB * (IDIM/4); i += THREADS) {
        int n = i >> 7, k4 = i & 127;
        cp16(sb + OFF_X + (n*XP + k4*4)*4, gx_int + (size_t)(n0+n)*IDIM + k4*4);
    }
    for (int i = tid; i < NB * (HDIM/4); i += THREADS) {
        int n = i >> 5, q4 = i & 31;
        cp16(sb + OFF_H + (n*HP + q4*4)*4, gx + (size_t)(n0+n)*HDIM + q4*4);
    }
    CP_COMMIT(); CP_WAIT0();
    __syncthreads();

    // Prologue: W slabs 0,1 into ring slots 0,1 (one commit group per slab).
    #pragma unroll 1
    for (int p = 0; p < 2; ++p) {
        const unsigned char* src = g_wpack + (size_t)p * WSLAB + tid * 128;
        uint32_t d = sb + OFF_W + p * WSLAB + tid * 128;
        #pragma unroll
        for (int v = 0; v < 8; ++v) cp16(d + v*16, src + v*16);
        CP_COMMIT();
    }

    // Z generator: slab ls of current layer -> Z slot (hi/lo bf16, swizzled).
    const int zn = tid >> 3, zkb = tid & 7;
    auto zgen = [&](int ls, int slot) {
        unsigned char* zp = sm + OFF_Z + slot * ZSLAB;
        const unsigned zoff = SW128(zn * 128 + zkb * 16);
        float v[8];
        if (ls < CHUNKS * SPC) {
            const int c = ls >> 3, j = ls & 7;
            const float m = (c < HDIM) ? hs[zn*HP + c] : 1.0f;
            const float* xp = &xs[zn*XP + j*64 + zkb*8];
            #pragma unroll
            for (int e = 0; e < 8; ++e) v[e] = m * xp[e];
        } else {
            const int j = ls - CHUNKS * SPC;
            #pragma unroll
            for (int e = 0; e < 8; ++e) {
                const int kg = j*64 + zkb*8 + e;
                v[e] = (kg < HDIM) ? hs[zn*HP + kg] : (kg == HDIM ? 1.f : 0.f);
            }
        }
        unsigned hi[4], lo[4];
        #pragma unroll
        for (int e = 0; e < 4; ++e) split2(v[2*e], v[2*e+1], hi[e], lo[e]);
        *(uint4*)(zp + zoff)        = make_uint4(hi[0], hi[1], hi[2], hi[3]);
        *(uint4*)(zp + 4096 + zoff) = make_uint4(lo[0], lo[1], lo[2], lo[3]);
    };

    int s = 0;
    for (int layer = 0; layer < NLAYER; ++layer) {
        float acc[4][4];
        #pragma unroll
        for (int t = 0; t < 4; ++t)
            #pragma unroll
            for (int i = 0; i < 4; ++i) acc[t][i] = 0.f;

        zgen(0, 0);                     // Z for first slab of this layer

        for (int ls = 0; ls < SPL; ++ls, ++s) {
            CP_WAIT1();                 // W slab s landed (<=1 newer group pending)
            __syncthreads();            // W(s) + Z(ls) visible; slot (s+2)%3 free

            const uint32_t wb = sb + OFF_W + (s % 3) * WSLAB;
            const uint32_t zb = sb + OFF_Z + (ls & 1) * ZSLAB;

            #pragma unroll
            for (int kk = 0; kk < 4; ++kk) {
                uint32_t ah[4], al[4], bh[8], bl[8];
                ldsm4(ah[0], ah[1], ah[2], ah[3], wb + SW128(aoff + kk*32));
                ldsm4(al[0], al[1], al[2], al[3], wb + 16384 + SW128(aoff + kk*32));
                ldsm4(bh[0], bh[1], bh[2], bh[3], zb + SW128(boff + kk*32));
                ldsm4(bh[4], bh[5], bh[6], bh[7], zb + SW128(boff + 2048 + kk*32));
                ldsm4(bl[0], bl[1], bl[2], bl[3], zb + 4096 + SW128(boff + kk*32));
                ldsm4(bl[4], bl[5], bl[6], bl[7], zb + 4096 + SW128(boff + 2048 + kk*32));
                #pragma unroll
                for (int t = 0; t < 4; ++t) {
                    mma_bf16(acc[t], ah, bh[2*t], bh[2*t+1]);   // hi*hi
                    mma_bf16(acc[t], al, bh[2*t], bh[2*t+1]);   // lo*hi
                    mma_bf16(acc[t], ah, bl[2*t], bl[2*t+1]);   // hi*lo
                }
            }

            // Prefetch W slab s+2 (wrap keeps slot map consistent; NSLAB%3==0).
            {
                const int pf = (s + 2) % NSLAB;
                const unsigned char* src = g_wpack + (size_t)pf * WSLAB + tid * 128;
                uint32_t d = sb + OFF_W + (pf % 3) * WSLAB + tid * 128;
                #pragma unroll
                for (int v = 0; v < 8; ++v) cp16(d + v*16, src + v*16);
                CP_COMMIT();
            }

            if (ls + 1 < SPL) zgen(ls + 1, (ls + 1) & 1);
        }

        // ---- layer epilogue: relu -> hs, or write gout ----
        // d-frag: c0:(q=16w+l/4, n=2(l%4)) c1:n+1 c2:q+8 c3:q+8,n+1  per n-tile t (n+=8t)
        const int qb = 16*wid + (lid >> 2);
        const int nb = 2 * (lid & 3);
        if (layer < NLAYER - 1) {
            #pragma unroll
            for (int t = 0; t < 4; ++t) {
                const int n = 8*t + nb;
                hs[(n  )*HP + qb    ] = fmaxf(acc[t][0], 0.f);
                hs[(n+1)*HP + qb    ] = fmaxf(acc[t][1], 0.f);
                hs[(n  )*HP + qb + 8] = fmaxf(acc[t][2], 0.f);
                hs[(n+1)*HP + qb + 8] = fmaxf(acc[t][3], 0.f);
            }
        } else {
            #pragma unroll
            for (int t = 0; t < 4; ++t) {
                const int n = 8*t + nb;
                gout[(size_t)(n0 + n    )*HDIM + qb    ] = acc[t][0];
                gout[(size_t)(n0 + n + 1)*HDIM + qb    ] = acc[t][1];
                gout[(size_t)(n0 + n    )*HDIM + qb + 8] = acc[t][2];
                gout[(size_t)(n0 + n + 1)*HDIM + qb + 8] = acc[t][3];
            }
        }
        __syncthreads();                // hs complete before next layer's zgen
    }
}

extern "C" void kernel_launch(void* const* d_in, const int* in_sizes, int n_in,
                              void* d_out, int out_size)
{
    const float *int_x = nullptr, *x = nullptr, *W = nullptr, *b = nullptr;
    for (int i = 0; i < n_in; ++i) {
        const int sz = in_sizes[i];
        if      (sz == NSAMP*IDIM)          int_x = (const float*)d_in[i];
        else if (sz == NSAMP*HDIM)          x     = (const float*)d_in[i];
        else if (sz == NLAYER*LSTRIDE*IDIM) W     = (const float*)d_in[i];
        else if (sz == NLAYER*LSTRIDE)      b     = (const float*)d_in[i];
    }

    prep_kernel<<<NSLAB, 256>>>(W, b);

    cudaFuncSetAttribute(inet_mma_kernel, cudaFuncAttributeMaxDynamicSharedMemorySize,
                         SMEM_ALLOC);
    inet_mma_kernel<<<NSAMP/NB, THREADS, SMEM_ALLOC>>>(int_x, x, (float*)d_out);
}